// round 8
// baseline (speedup 1.0000x reference)
#include <cuda_runtime.h>
#include <cstddef>
#include <cstdint>

#define BATCH 64
#define SEQ   2048
#define DIM   512
#define NFINE 16
#define MSPAN 512

typedef unsigned long long u64;

// Blackwell packed fp32x2 math (SASS FFMA2/FADD2) — PTX-only.
#define FMA2(d,a,b,c) asm("fma.rn.f32x2 %0, %1, %2, %3;" : "=l"(d) : "l"(a), "l"(b), "l"(c))
#define ADD2(d,a,b)   asm("add.rn.f32x2 %0, %1, %2;" : "=l"(d) : "l"(a), "l"(b))

// g_ctr[0] = total valid spans, [1] = B1 ticket, [2] = B2 ticket, [3] = pad.
__device__ int g_ctr[4];
__device__ int g_spanP[BATCH * MSPAN];   // span start token (global index)
__device__ int g_spanE[BATCH * MSPAN];   // span end token (global, exclusive)
__device__ int g_spanW[BATCH * MSPAN];   // output span slot (b*MSPAN + k)
// span feature scratch (L2-resident working set in practice)
__device__ __align__(16) float g_F[BATCH * MSPAN * DIM];

// ---------------------------------------------------------------------------
// Kernel A: per batch row, compact B-tag positions via block scan, emit
// (start, end, out_idx) triples to the global compact worklist.
// ---------------------------------------------------------------------------
__global__ void __launch_bounds__(256) span_index_kernel(
    const int* __restrict__ labels, const int* __restrict__ pB)
{
    __shared__ int Bpos[MSPAN + 1];
    __shared__ int s_base, s_n, s_nbtot;
    __shared__ int wsum[8];

    const int b = blockIdx.x;
    const int t = threadIdx.x;
    const int cB = *pB;
    const int* row = labels + (size_t)b * SEQ;

    const int s0 = t * 8;
    int flags[8];
    int cnt = 0;
#pragma unroll
    for (int j = 0; j < 8; j++) {
        flags[j] = (row[s0 + j] == cB) ? 1 : 0;
        cnt += flags[j];
    }

    const int lane = t & 31;
    const int warp = t >> 5;
    int inc = cnt;
#pragma unroll
    for (int o = 1; o < 32; o <<= 1) {
        int v = __shfl_up_sync(0xffffffffu, inc, o);
        if (lane >= o) inc += v;
    }
    if (lane == 31) wsum[warp] = inc;
    __syncthreads();
    if (t < 8) {
        int v = wsum[t];
#pragma unroll
        for (int o = 1; o < 8; o <<= 1) {
            int u = __shfl_up_sync(0xffu, v, o);
            if (t >= o) v += u;
        }
        wsum[t] = v;
    }
    __syncthreads();
    int excl = inc - cnt + (warp > 0 ? wsum[warp - 1] : 0);

    int idx = excl;
#pragma unroll
    for (int j = 0; j < 8; j++) {
        if (flags[j]) {
            if (idx <= MSPAN) Bpos[idx] = s0 + j;
            idx++;
        }
    }
    if (t == 255) {
        int nBtot = excl + cnt;
        int n = nBtot < MSPAN ? nBtot : MSPAN;
        s_nbtot = nBtot;
        s_n = n;
        s_base = atomicAdd(&g_ctr[0], n);
    }
    __syncthreads();

    const int n = s_n;
    const int base = s_base;
    const int nbtot = s_nbtot;
    for (int k = t; k < n; k += 256) {
        int p = Bpos[k];
        int pend = (k + 1 < nbtot) ? Bpos[k + 1] : SEQ;
        g_spanP[base + k] = b * SEQ + p;
        g_spanE[base + k] = b * SEQ + pend;
        g_spanW[base + k] = b * MSPAN + k;
    }
}

// ---------------------------------------------------------------------------
// Kernel B1: warp-per-span segment-sum into g_F. No smem, no W — minimal regs
// for max occupancy. Dynamic ticket for balance.
// ---------------------------------------------------------------------------
__global__ void __launch_bounds__(256, 5) seg_sum_kernel(
    const float* __restrict__ hidden,
    const int*   __restrict__ labels, // flat [BATCH*SEQ]
    const int*   __restrict__ pI)
{
    const int cI = *pI;
    const int lane = threadIdx.x & 31;
    const int total = g_ctr[0];

    for (;;) {
        int i;
        if (lane == 0) i = atomicAdd(&g_ctr[1], 1);
        i = __shfl_sync(0xffffffffu, i, 0);
        if (i >= total) break;

        const int P = __ldg(g_spanP + i);
        const int E = __ldg(g_spanE + i);

        u64 F[8];
        {
            const ulonglong2* h =
                reinterpret_cast<const ulonglong2*>(hidden + (size_t)P * DIM);
            ulonglong2 a = __ldg(h + lane);
            ulonglong2 b = __ldg(h + lane + 32);
            ulonglong2 c = __ldg(h + lane + 64);
            ulonglong2 d = __ldg(h + lane + 96);
            F[0] = a.x; F[1] = a.y; F[2] = b.x; F[3] = b.y;
            F[4] = c.x; F[5] = c.y; F[6] = d.x; F[7] = d.y;
        }
        for (int s = P + 1; s < E; s += 32) {
            int ss = s + lane;
            bool hit = (ss < E) && (__ldg(labels + ss) == cI);
            unsigned m = __ballot_sync(0xffffffffu, hit);
            while (m) {
                int j = __ffs(m) - 1;
                m &= m - 1;
                const ulonglong2* h = reinterpret_cast<const ulonglong2*>(
                    hidden + (size_t)(s + j) * DIM);
                ulonglong2 a = __ldg(h + lane);
                ulonglong2 b = __ldg(h + lane + 32);
                ulonglong2 c = __ldg(h + lane + 64);
                ulonglong2 d = __ldg(h + lane + 96);
                ADD2(F[0], F[0], a.x); ADD2(F[1], F[1], a.y);
                ADD2(F[2], F[2], b.x); ADD2(F[3], F[3], b.y);
                ADD2(F[4], F[4], c.x); ADD2(F[5], F[5], c.y);
                ADD2(F[6], F[6], d.x); ADD2(F[7], F[7], d.y);
            }
        }
        // write feature row: coalesced STG.128
        ulonglong2* dst = reinterpret_cast<ulonglong2*>(g_F + (size_t)i * DIM);
#pragma unroll
        for (int j = 0; j < 4; j++)
            dst[lane + 32 * j] = make_ulonglong2(F[2 * j], F[2 * j + 1]);
    }
}

// ---------------------------------------------------------------------------
// Tree-fold 4 per-lane partials across the warp in 6 SHFLs; lanes
// {0,8,16,24} write floc {0,1,2,3}.
// ---------------------------------------------------------------------------
__device__ __forceinline__ void fold_write(
    const float sc[4], float* __restrict__ dst, int lane)
{
    float send0 = (lane & 16) ? sc[0] : sc[2];
    float r0 = __shfl_xor_sync(0xffffffffu, send0, 16);
    float n0 = ((lane & 16) ? sc[2] : sc[0]) + r0;
    float send1 = (lane & 16) ? sc[1] : sc[3];
    float r1 = __shfl_xor_sync(0xffffffffu, send1, 16);
    float n1 = ((lane & 16) ? sc[3] : sc[1]) + r1;

    float send = (lane & 8) ? n0 : n1;
    float r = __shfl_xor_sync(0xffffffffu, send, 8);
    float v = ((lane & 8) ? n1 : n0) + r;

    v += __shfl_xor_sync(0xffffffffu, v, 4);
    v += __shfl_xor_sync(0xffffffffu, v, 2);
    v += __shfl_xor_sync(0xffffffffu, v, 1);

    if ((lane & 7) == 0) {
        int floc = (((lane >> 4) & 1) << 1) | ((lane >> 3) & 1);
        dst[floc] = v;
    }
}

// ---------------------------------------------------------------------------
// Kernel B2: dense projection of g_F rows. 128-thread blocks (4 warps);
// warp w owns filters 4w..4w+3 register-resident. Batch of 4 spans/ticket:
//   phase 1: warp w streams F row base+w from L2 into smem (uniform work!)
//   phase 2: each warp projects all 4 rows for its own 4 filters.
// ---------------------------------------------------------------------------
__global__ void __launch_bounds__(128, 4) project_kernel(
    const float* __restrict__ slot,   // [DIM][NFINE]
    float* __restrict__ out)          // [BATCH][MSPAN][NFINE]
{
    __shared__ __align__(16) float pool[NFINE * DIM];  // W staging, then F rows
    __shared__ int s_ticket;
    __shared__ int s_O[4];
    __shared__ int s_val[4];

    const int tid  = threadIdx.x;
    const int lane = tid & 31;
    const int warp = tid >> 5;

    // stage W transposed: pool[f*512 + d] = slot[d*16 + f]
    for (int i = tid; i < DIM * NFINE; i += 128) {
        int d = i >> 4;
        int f = i & 15;
        pool[f * DIM + d] = slot[i];
    }
    __syncthreads();

    // this lane's W: 4 filters x 16 dims = 32 u64, loaded once
    u64 W2[4][8];
#pragma unroll
    for (int fl = 0; fl < 4; fl++) {
        const int f = 4 * warp + fl;
#pragma unroll
        for (int j = 0; j < 4; j++) {
            ulonglong2 v = *reinterpret_cast<const ulonglong2*>(
                &pool[f * DIM + 4 * lane + 128 * j]);
            W2[fl][2 * j]     = v.x;
            W2[fl][2 * j + 1] = v.y;
        }
    }

    const int total = g_ctr[0];

    for (;;) {
        __syncthreads();  // protect pool/s_ticket reuse
        if (tid == 0) s_ticket = atomicAdd(&g_ctr[2], 4);
        __syncthreads();
        const int base = s_ticket;
        if (base >= total) break;

        // phase 1: uniform coalesced copy of F row (base+warp) into smem
        const int i = base + warp;
        const bool val = (i < total);
        if (lane == 0) {
            s_val[warp] = val ? 1 : 0;
            if (val) s_O[warp] = __ldg(g_spanW + i);
        }
        if (val) {
            const ulonglong2* src =
                reinterpret_cast<const ulonglong2*>(g_F + (size_t)i * DIM);
#pragma unroll
            for (int j = 0; j < 4; j++) {
                ulonglong2 v = __ldg(src + lane + 32 * j);
                *reinterpret_cast<ulonglong2*>(
                    &pool[warp * DIM + 4 * lane + 128 * j]) = v;
            }
        }
        __syncthreads();

        // phase 2: project all 4 rows for this warp's 4 filters
#pragma unroll
        for (int s = 0; s < 4; s++) {
            if (!s_val[s]) continue;
            u64 F2[8];
#pragma unroll
            for (int j = 0; j < 4; j++) {
                ulonglong2 v = *reinterpret_cast<const ulonglong2*>(
                    &pool[s * DIM + 4 * lane + 128 * j]);
                F2[2 * j]     = v.x;
                F2[2 * j + 1] = v.y;
            }
            float sc[4];
#pragma unroll
            for (int fl = 0; fl < 4; fl++) {
                u64 acc = 0ull;
#pragma unroll
                for (int k = 0; k < 8; k++) FMA2(acc, F2[k], W2[fl][k], acc);
                float2 p = *reinterpret_cast<float2*>(&acc);
                sc[fl] = p.x + p.y;
            }
            fold_write(sc, out + (size_t)s_O[s] * NFINE + 4 * warp, lane);
        }
    }
}

extern "C" void kernel_launch(void* const* d_in, const int* in_sizes, int n_in,
                              void* d_out, int out_size)
{
    const float* hidden = (const float*)d_in[0];
    const float* slot   = (const float*)d_in[1];
    const int*   labels = (const int*)d_in[2];
    const int*   pB     = (const int*)d_in[3];
    const int*   pI     = (const int*)d_in[4];
    float* out = (float*)d_out;

    void* ctr_ptr = nullptr;
    cudaGetSymbolAddress(&ctr_ptr, g_ctr);
    cudaMemsetAsync(ctr_ptr, 0, 4 * sizeof(int), 0);
    cudaMemsetAsync(out, 0, (size_t)out_size * sizeof(float), 0);

    span_index_kernel<<<BATCH, 256>>>(labels, pB);
    seg_sum_kernel<<<148 * 5, 256>>>(hidden, labels, pI);
    project_kernel<<<148 * 4, 128>>>(slot, out);
}

// round 9
// speedup vs baseline: 1.8746x; 1.8746x over previous
#include <cuda_runtime.h>
#include <cstddef>
#include <cstdint>

#define BATCH 64
#define SEQ   2048
#define DIM   512
#define NFINE 16
#define MSPAN 512
#define GRID  (148 * 3)

typedef unsigned long long u64;

// Blackwell packed fp32x2 math (SASS FFMA2/FADD2) — PTX-only.
#define FMA2(d,a,b,c) asm("fma.rn.f32x2 %0, %1, %2, %3;" : "=l"(d) : "l"(a), "l"(b), "l"(c))
#define ADD2(d,a,b)   asm("add.rn.f32x2 %0, %1, %2;" : "=l"(d) : "l"(a), "l"(b))

// [0]=total spans, [1]=work ticket, [2]=unused, [3]=index-done counter
__device__ int  g_ctr[4];
__device__ int2 g_spanPE[BATCH * MSPAN];  // (start, end) token, global indices
__device__ int  g_spanW [BATCH * MSPAN];  // output span slot (b*MSPAN + k)

// ---------------------------------------------------------------------------
// Tree-fold 4 per-lane partials across the warp in 6 SHFLs; lanes
// {0,8,16,24} write floc {0,1,2,3}.
// ---------------------------------------------------------------------------
__device__ __forceinline__ void fold_write(
    const float sc[4], float* __restrict__ dst, int lane)
{
    float send0 = (lane & 16) ? sc[0] : sc[2];
    float r0 = __shfl_xor_sync(0xffffffffu, send0, 16);
    float n0 = ((lane & 16) ? sc[2] : sc[0]) + r0;
    float send1 = (lane & 16) ? sc[1] : sc[3];
    float r1 = __shfl_xor_sync(0xffffffffu, send1, 16);
    float n1 = ((lane & 16) ? sc[3] : sc[1]) + r1;

    float send = (lane & 8) ? n0 : n1;
    float r = __shfl_xor_sync(0xffffffffu, send, 8);
    float v = ((lane & 8) ? n1 : n0) + r;

    v += __shfl_xor_sync(0xffffffffu, v, 4);
    v += __shfl_xor_sync(0xffffffffu, v, 2);
    v += __shfl_xor_sync(0xffffffffu, v, 1);

    if ((lane & 7) == 0) {
        int floc = (((lane >> 4) & 1) << 1) | ((lane >> 3) & 1);
        dst[floc] = v;
    }
}

// ---------------------------------------------------------------------------
// Segment-sum one span into 8 packed f32x2 regs (lane owns dims 4*lane+128j).
// ---------------------------------------------------------------------------
__device__ __forceinline__ void accum_span(
    u64 F[8], const float* __restrict__ hidden,
    const int* __restrict__ labels, int P, int E, int cI, int lane)
{
    {
        const ulonglong2* h =
            reinterpret_cast<const ulonglong2*>(hidden + (size_t)P * DIM);
        ulonglong2 a = __ldg(h + lane);
        ulonglong2 b = __ldg(h + lane + 32);
        ulonglong2 c = __ldg(h + lane + 64);
        ulonglong2 d = __ldg(h + lane + 96);
        F[0] = a.x; F[1] = a.y; F[2] = b.x; F[3] = b.y;
        F[4] = c.x; F[5] = c.y; F[6] = d.x; F[7] = d.y;
    }
    for (int s = P + 1; s < E; s += 32) {
        int ss = s + lane;
        bool hit = (ss < E) && (__ldg(labels + ss) == cI);
        unsigned m = __ballot_sync(0xffffffffu, hit);
        while (m) {
            int j = __ffs(m) - 1;
            m &= m - 1;
            const ulonglong2* h = reinterpret_cast<const ulonglong2*>(
                hidden + (size_t)(s + j) * DIM);
            ulonglong2 a = __ldg(h + lane);
            ulonglong2 b = __ldg(h + lane + 32);
            ulonglong2 c = __ldg(h + lane + 64);
            ulonglong2 d = __ldg(h + lane + 96);
            ADD2(F[0], F[0], a.x); ADD2(F[1], F[1], a.y);
            ADD2(F[2], F[2], b.x); ADD2(F[3], F[3], b.y);
            ADD2(F[4], F[4], c.x); ADD2(F[5], F[5], c.y);
            ADD2(F[6], F[6], d.x); ADD2(F[7], F[7], d.y);
        }
    }
}

// ---------------------------------------------------------------------------
// Fused kernel. Grid = 444 blocks, all resident (launch_bounds(256,4)).
// Blocks 0..63 build the compact worklist first (shared-mem scan), then
// everybody stages W, spins on the done counter, and consumes 2-span tickets.
// ---------------------------------------------------------------------------
__global__ void __launch_bounds__(256, 4) fused_kernel(
    const float* __restrict__ hidden,
    const float* __restrict__ slot,   // [DIM][NFINE]
    const int*   __restrict__ labels, // flat [BATCH*SEQ]
    const int*   __restrict__ pB,
    const int*   __restrict__ pI,
    float* __restrict__ out)          // [BATCH][MSPAN][NFINE]
{
    __shared__ __align__(16) float Wsh[NFINE * DIM];  // Wsh[f*512 + d], 32KB
    __shared__ int Bpos[MSPAN + 1];
    __shared__ int wsum[8];

    const int tid  = threadIdx.x;
    const int lane = tid & 31;
    const int warp = tid >> 5;

    // ---- phase 0: first 64 blocks build the worklist for batch row b ----
    if (blockIdx.x < BATCH) {
        const int b = blockIdx.x;
        const int cB = *pB;
        const int* row = labels + (size_t)b * SEQ;

        const int s0 = tid * 8;
        int flags[8];
        int cnt = 0;
#pragma unroll
        for (int j = 0; j < 8; j++) {
            flags[j] = (row[s0 + j] == cB) ? 1 : 0;
            cnt += flags[j];
        }
        int inc = cnt;
#pragma unroll
        for (int o = 1; o < 32; o <<= 1) {
            int v = __shfl_up_sync(0xffffffffu, inc, o);
            if (lane >= o) inc += v;
        }
        if (lane == 31) wsum[warp] = inc;
        __syncthreads();
        if (tid < 8) {
            int v = wsum[tid];
#pragma unroll
            for (int o = 1; o < 8; o <<= 1) {
                int u = __shfl_up_sync(0xffu, v, o);
                if (tid >= o) v += u;
            }
            wsum[tid] = v;
        }
        __syncthreads();
        int excl = inc - cnt + (warp > 0 ? wsum[warp - 1] : 0);

        int idx = excl;
#pragma unroll
        for (int j = 0; j < 8; j++) {
            if (flags[j]) {
                if (idx <= MSPAN) Bpos[idx] = s0 + j;
                idx++;
            }
        }
        __syncthreads();
        int nbtot = wsum[7];                       // total B tags in row
        int n = nbtot < MSPAN ? nbtot : MSPAN;
        __shared__ int s_base;
        if (tid == 0) s_base = atomicAdd(&g_ctr[0], n);
        __syncthreads();
        const int base = s_base;
        for (int k = tid; k < n; k += 256) {
            int p = Bpos[k];
            int pend = (k + 1 < nbtot) ? Bpos[k + 1] : SEQ;
            g_spanPE[base + k] = make_int2(b * SEQ + p, b * SEQ + pend);
            g_spanW[base + k]  = b * MSPAN + k;
        }
        __syncthreads();
        if (tid == 0) {
            __threadfence();                       // release worklist
            atomicAdd(&g_ctr[3], 1);
        }
    }

    // ---- stage W transposed while indexers finish ----
    for (int i = tid; i < DIM * NFINE; i += 256) {
        int d = i >> 4;
        int f = i & 15;
        Wsh[f * DIM + d] = slot[i];
    }

    // ---- spin until all 64 indexer blocks are done ----
    if (tid == 0) {
        while (atomicAdd(&g_ctr[3], 0) < BATCH) { }
        __threadfence();                           // acquire
    }
    __syncthreads();

    const ulonglong2* W2 = reinterpret_cast<const ulonglong2*>(Wsh);
    const int cI = *pI;
    const int total = g_ctr[0];

    // ---- main loop: 2 spans per dynamic ticket ----
    for (;;) {
        int i;
        if (lane == 0) i = atomicAdd(&g_ctr[1], 2);
        i = __shfl_sync(0xffffffffu, i, 0);
        if (i >= total) break;
        const bool v1 = (i + 1 < total);

        int2 pe0 = __ldg(g_spanPE + i);
        int2 pe1 = v1 ? __ldg(g_spanPE + i + 1) : make_int2(pe0.x, pe0.x);
        const int O0 = __ldg(g_spanW + i);
        const int O1 = v1 ? __ldg(g_spanW + i + 1) : 0;

        u64 F0[8], F1[8];
        accum_span(F0, hidden, labels, pe0.x, pe0.y, cI, lane);
        if (v1) {
            accum_span(F1, hidden, labels, pe1.x, pe1.y, cI, lane);
        } else {
#pragma unroll
            for (int k = 0; k < 8; k++) F1[k] = 0ull;
        }

        // projection: 4 groups of 4 filters; W LDS shared by both spans
#pragma unroll
        for (int g = 0; g < 4; g++) {
            float sc0[4], sc1[4];
#pragma unroll
            for (int jj = 0; jj < 4; jj++) {
                const int f = 4 * g + jj;
                ulonglong2 wa = W2[f * 128 + lane];
                ulonglong2 wb = W2[f * 128 + lane + 32];
                ulonglong2 wc = W2[f * 128 + lane + 64];
                ulonglong2 wd = W2[f * 128 + lane + 96];
                u64 a0 = 0ull, a1 = 0ull;
                FMA2(a0, F0[0], wa.x, a0);  FMA2(a1, F1[0], wa.x, a1);
                FMA2(a0, F0[1], wa.y, a0);  FMA2(a1, F1[1], wa.y, a1);
                FMA2(a0, F0[2], wb.x, a0);  FMA2(a1, F1[2], wb.x, a1);
                FMA2(a0, F0[3], wb.y, a0);  FMA2(a1, F1[3], wb.y, a1);
                FMA2(a0, F0[4], wc.x, a0);  FMA2(a1, F1[4], wc.x, a1);
                FMA2(a0, F0[5], wc.y, a0);  FMA2(a1, F1[5], wc.y, a1);
                FMA2(a0, F0[6], wd.x, a0);  FMA2(a1, F1[6], wd.x, a1);
                FMA2(a0, F0[7], wd.y, a0);  FMA2(a1, F1[7], wd.y, a1);
                float2 p0 = *reinterpret_cast<float2*>(&a0);
                float2 p1 = *reinterpret_cast<float2*>(&a1);
                sc0[jj] = p0.x + p0.y;
                sc1[jj] = p1.x + p1.y;
            }
            fold_write(sc0, out + (size_t)O0 * NFINE + 4 * g, lane);
            if (v1) fold_write(sc1, out + (size_t)O1 * NFINE + 4 * g, lane);
        }
    }
}

extern "C" void kernel_launch(void* const* d_in, const int* in_sizes, int n_in,
                              void* d_out, int out_size)
{
    const float* hidden = (const float*)d_in[0];
    const float* slot   = (const float*)d_in[1];
    const int*   labels = (const int*)d_in[2];
    const int*   pB     = (const int*)d_in[3];
    const int*   pI     = (const int*)d_in[4];
    float* out = (float*)d_out;

    void* ctr_ptr = nullptr;
    cudaGetSymbolAddress(&ctr_ptr, g_ctr);
    cudaMemsetAsync(ctr_ptr, 0, 4 * sizeof(int), 0);
    cudaMemsetAsync(out, 0, (size_t)out_size * sizeof(float), 0);

    fused_kernel<<<GRID, 256>>>(hidden, slot, labels, pB, pI, out);
}